// round 11
// baseline (speedup 1.0000x reference)
#include <cuda_runtime.h>
#include <cstdint>

// Conv(5x5, SAME) over [256,1,512,512] + FastLIF + FastLI temporal scan.
// ONE WARP PER BLOCK, tile 16x8 (grid 32x64 = 2048 blocks -> ~14 warps/SM,
// double R10's residency at IDENTICAL LDS-wavefront and FMA cost/output).
// Each thread: 2 rows x 2 cols. smem row stride 24 floats makes every
// 16-lane LDS.64 phase bank-conflict-free. Private triple-buffered smem
// filled by cp.async (zfill OOB), prefetch depth 2, warp-local sync only.

#define TT 256
#define HH 512
#define WW 512
#define HW (HH*WW)

#define QW 16        // tile width (outputs)
#define QH 8         // tile height (outputs)
#define NT 32        // threads per block (1 warp)
#define SWP 24       // smem row stride in floats (cols x0-4 .. x0+19)
#define SHR 12       // smem rows (8 + 4 halo)
#define WBUF (SHR*SWP)        // 288 floats used per buffer
#define WBUFP (WBUF + 4)      // +4 floats per-buffer scratch (zfill dump)
#define F4R 6                 // float4 per smem row
#define FILLV (SHR*F4R)       // 72 float4 copies per tile
#define PF 3                  // ceil(72/32) fill slots per lane

#define ALPHA_LIF 0.85f
#define V_TH 2.0f
#define ALPHA_LI 0.9f

__device__ __forceinline__ void cp_async16(uint32_t dst_smem, const void* src, int srcsize) {
    asm volatile("cp.async.cg.shared.global [%0], [%1], 16, %2;\n"
                 :: "r"(dst_smem), "l"(src), "r"(srcsize));
}
__device__ __forceinline__ void cp_commit() {
    asm volatile("cp.async.commit_group;\n");
}
__device__ __forceinline__ void cp_wait1() {
    asm volatile("cp.async.wait_group 1;\n");
}

__global__ __launch_bounds__(NT)
void snn_fused_kernel(const float* __restrict__ x,
                      const float* __restrict__ kern,
                      float* __restrict__ out)
{
    // 3 buffers of WBUFP floats (per-buffer scratch at offset WBUF)
    __shared__ __align__(16) float sm[3 * WBUFP];

    const int lane = threadIdx.x;
    const int tc   = lane & 7;        // col group: output cols x0+2tc, +1
    const int rp   = lane >> 3;       // row-pair: output rows y0+2rp, +1

    const int x0 = blockIdx.x * QW;
    const int y0 = blockIdx.y * QH;

    // 5x5 weights in registers (uniform broadcast)
    float wgt[25];
#pragma unroll
    for (int i = 0; i < 25; i++) wgt[i] = __ldg(kern + i);

    // ---- Precompute this lane's PF cp.async fill slots (invariant over t) ----
    // Slot j copies float4 #(lane + j*32) of the 12-row x 6-float4 tile.
    // smem col 0 <-> global col x0-4 ; smem row 0 <-> global row y0-2.
    // Inactive slots target the per-buffer scratch at offset WBUF.
    int soff[PF], goff[PF], ssz[PF];
#pragma unroll
    for (int j = 0; j < PF; j++) {
        int i = lane + j * 32;
        if (i < FILLV) {
            int rr = i / F4R;
            int c4 = i - rr * F4R;
            int gy = y0 - 2 + rr;
            int gx = x0 - 4 + 4 * c4;
            bool v = (gy >= 0) && (gy < HH) && (gx >= 0) && (gx <= WW - 4);
            soff[j] = rr * SWP + 4 * c4;
            goff[j] = v ? (gy * WW + gx) : 0;
            ssz[j]  = v ? 16 : 0;
        } else {
            soff[j] = WBUF;   // per-buffer scratch, rotation-safe
            goff[j] = 0;
            ssz[j]  = 0;
        }
    }

    // Buffer base addresses (u32 smem space), rotated each step
    uint32_t c0 = (uint32_t)__cvta_generic_to_shared(&sm[0]);
    uint32_t c1 = c0 + 4u * WBUFP;
    uint32_t c2 = c0 + 8u * WBUFP;
    int bo = 0;                        // front buffer float-offset

    // ---- Prefetch timesteps 0 and 1 ----
    {
        const float* xt = x;
#pragma unroll
        for (int j = 0; j < PF; j++) cp_async16(c0 + 4u * soff[j], xt + goff[j], ssz[j]);
        cp_commit();
        xt += HW;
#pragma unroll
        for (int j = 0; j < PF; j++) cp_async16(c1 + 4u * soff[j], xt + goff[j], ssz[j]);
        cp_commit();
    }

    // LIF / LI state: 2 rows x 2 cols
    float s1[4] = {0.f, 0.f, 0.f, 0.f};
    float s2[4] = {0.f, 0.f, 0.f, 0.f};

    const float* xp = x + 2 * (size_t)HW;                        // source for t+2
    float* op = out + (size_t)(y0 + 2 * rp) * WW + x0 + 2 * tc;  // row 0 of pair
    const int rbase = (2 * rp) * SWP + 2 * tc + 2;               // smem read base (m0)

    for (int t = 0; t < TT; t++) {
        cp_wait1();      // this lane's copies for step t have landed
        __syncwarp();    // other lanes' copies visible

        // Prefetch t+2 into the freed buffer (c2)
        if (t + 2 < TT) {
#pragma unroll
            for (int j = 0; j < PF; j++)
                cp_async16(c2 + 4u * soff[j], xp + goff[j], ssz[j]);
        }
        cp_commit();     // unconditional: uniform wait_group accounting
        xp += HW;

        // ---- 5x5 conv: 2 rows x 2 cols from 6 streamed input rows ----
        // Per row: window = smem floats [2tc+2, 2tc+7] -> 3x LDS.64 (8B
        // aligned). Stride 24: each 16-lane phase (2 row-pairs x 8 tcs)
        // covers both 16-bank halves -> conflict-free.
        const float* rb = &sm[rbase + bo];

        float a0 = 0.f, a1 = 0.f;   // output row 2rp,   cols 0,1
        float d0 = 0.f, d1 = 0.f;   // output row 2rp+1, cols 0,1
#pragma unroll
        for (int j = 0; j < 6; j++) {
            const float* rowp = rb + j * SWP;
            float2 u0 = *(const float2*)(rowp + 0);   // m0,m1
            float2 u1 = *(const float2*)(rowp + 2);   // m2,m3
            float2 u2 = *(const float2*)(rowp + 4);   // m4,m5
            float m0 = u0.x, m1 = u0.y, m2 = u1.x, m3 = u1.y, m4 = u2.x, m5 = u2.y;
            if (j < 5) {                     // row 2rp, vertical tap a=j
                const float* wa = wgt + j * 5;
                a0 = fmaf(wa[0], m0, a0); a0 = fmaf(wa[1], m1, a0);
                a0 = fmaf(wa[2], m2, a0); a0 = fmaf(wa[3], m3, a0);
                a0 = fmaf(wa[4], m4, a0);
                a1 = fmaf(wa[0], m1, a1); a1 = fmaf(wa[1], m2, a1);
                a1 = fmaf(wa[2], m3, a1); a1 = fmaf(wa[3], m4, a1);
                a1 = fmaf(wa[4], m5, a1);
            }
            if (j > 0) {                     // row 2rp+1, vertical tap a=j-1
                const float* wb = wgt + (j - 1) * 5;
                d0 = fmaf(wb[0], m0, d0); d0 = fmaf(wb[1], m1, d0);
                d0 = fmaf(wb[2], m2, d0); d0 = fmaf(wb[3], m3, d0);
                d0 = fmaf(wb[4], m4, d0);
                d1 = fmaf(wb[0], m1, d1); d1 = fmaf(wb[1], m2, d1);
                d1 = fmaf(wb[2], m3, d1); d1 = fmaf(wb[3], m4, d1);
                d1 = fmaf(wb[4], m5, d1);
            }
        }

        // ---- LIF fire + soft reset, LI readout, two float2 stores ----
        float acc[4] = {a0, a1, d0, d1};
        float o[4];
#pragma unroll
        for (int i = 0; i < 4; i++) {
            float v = fmaf(ALPHA_LIF, s1[i], acc[i]);
            float spk = (v >= V_TH) ? 1.0f : 0.0f;
            s1[i] = fmaf(spk, -V_TH, v);
            s2[i] = fmaf(ALPHA_LI, s2[i], spk);
            o[i] = s2[i];
        }
        float2 o0 = {o[0], o[1]};
        float2 o1 = {o[2], o[3]};
        *(float2*)op = o0;
        *(float2*)(op + WW) = o1;
        op += HW;

        // Rotate buffers (addresses and read offset together)
        uint32_t tb = c0; c0 = c1; c1 = c2; c2 = tb;
        bo += WBUFP; if (bo == 3 * WBUFP) bo = 0;
    }
}

extern "C" void kernel_launch(void* const* d_in, const int* in_sizes, int n_in,
                              void* d_out, int out_size)
{
    const float* x = (const float*)d_in[0];
    const float* k = (const float*)d_in[1];
    if (in_sizes[0] == 25) {  // defensive: swap if metadata order differs
        const float* tmp = x; x = k; k = tmp;
    }
    float* out = (float*)d_out;

    dim3 grid(WW / QW, HH / QH);   // 32 x 64 = 2048 one-warp blocks
    snn_fused_kernel<<<grid, NT>>>(x, k, out);
}

// round 12
// speedup vs baseline: 1.1908x; 1.1908x over previous
#include <cuda_runtime.h>
#include <cstdint>

// Conv(5x5, SAME) over [256,1,512,512] + FastLIF + FastLI temporal scan.
// ONE WARP PER BLOCK, tile 32x8 (grid 16x64 = 1024 blocks), each thread
// 2 rows x 4 cols — R10 structure, with the time loop UNROLLED BY 2:
// per iteration one wait_group + one __syncwarp covers TWO timesteps, and
// the two independent convs give 16 parallel FMA chains for latency hiding.
// 6 smem buffers; prefetch t+4,t+5 issued while t,t+1 are consumed and
// t+2,t+3 are in flight (cp.async zfill OOB, rotation-safe scratch).

#define TT 256
#define HH 512
#define WW 512
#define HW (HH*WW)

#define QW 32        // tile width (outputs)
#define QH 8         // tile height (outputs)
#define NT 32        // threads per block (1 warp)
#define SWP 40       // smem row stride (32+8 halo cols)
#define SHR 12       // smem rows (8+4 halo)
#define WBUF (SHR*SWP)        // 480 floats used per buffer
#define WBUFP (WBUF + 4)      // +4 floats per-buffer scratch (zfill dump)
#define NBUF 6
#define F4R 10                // float4 per smem row
#define FILLV (SHR*F4R)       // 120 float4 copies per tile
#define PF 4                  // ceil(120/32) fill slots per lane

#define ALPHA_LIF 0.85f
#define V_TH 2.0f
#define ALPHA_LI 0.9f

__device__ __forceinline__ void cp_async16(uint32_t dst_smem, const void* src, int srcsize) {
    asm volatile("cp.async.cg.shared.global [%0], [%1], 16, %2;\n"
                 :: "r"(dst_smem), "l"(src), "r"(srcsize));
}
__device__ __forceinline__ void cp_commit() {
    asm volatile("cp.async.commit_group;\n");
}
__device__ __forceinline__ void cp_wait2() {
    asm volatile("cp.async.wait_group 2;\n");
}

// 5x5 conv for 2 rows x 4 cols from 6 streamed smem rows (3x LDS.128 each)
__device__ __forceinline__ void conv8(const float* __restrict__ rb,
                                      const float* __restrict__ wgt,
                                      float* __restrict__ acc)
{
    float a0 = 0.f, a1 = 0.f, a2 = 0.f, a3 = 0.f;
    float d0 = 0.f, d1 = 0.f, d2 = 0.f, d3 = 0.f;
#pragma unroll
    for (int j = 0; j < 6; j++) {
        const float* rp = rb + j * SWP;
        float4 q0 = *(const float4*)(rp + 0);
        float4 q1 = *(const float4*)(rp + 4);
        float4 q2 = *(const float4*)(rp + 8);
        float m0 = q0.z, m1 = q0.w, m2 = q1.x, m3 = q1.y;
        float m4 = q1.z, m5 = q1.w, m6 = q2.x, m7 = q2.y;
        if (j < 5) {                     // upper row, vertical tap a=j
            const float* wa = wgt + j * 5;
            a0 = fmaf(wa[0], m0, a0); a0 = fmaf(wa[1], m1, a0);
            a0 = fmaf(wa[2], m2, a0); a0 = fmaf(wa[3], m3, a0);
            a0 = fmaf(wa[4], m4, a0);
            a1 = fmaf(wa[0], m1, a1); a1 = fmaf(wa[1], m2, a1);
            a1 = fmaf(wa[2], m3, a1); a1 = fmaf(wa[3], m4, a1);
            a1 = fmaf(wa[4], m5, a1);
            a2 = fmaf(wa[0], m2, a2); a2 = fmaf(wa[1], m3, a2);
            a2 = fmaf(wa[2], m4, a2); a2 = fmaf(wa[3], m5, a2);
            a2 = fmaf(wa[4], m6, a2);
            a3 = fmaf(wa[0], m3, a3); a3 = fmaf(wa[1], m4, a3);
            a3 = fmaf(wa[2], m5, a3); a3 = fmaf(wa[3], m6, a3);
            a3 = fmaf(wa[4], m7, a3);
        }
        if (j > 0) {                     // lower row, vertical tap a=j-1
            const float* wb = wgt + (j - 1) * 5;
            d0 = fmaf(wb[0], m0, d0); d0 = fmaf(wb[1], m1, d0);
            d0 = fmaf(wb[2], m2, d0); d0 = fmaf(wb[3], m3, d0);
            d0 = fmaf(wb[4], m4, d0);
            d1 = fmaf(wb[0], m1, d1); d1 = fmaf(wb[1], m2, d1);
            d1 = fmaf(wb[2], m3, d1); d1 = fmaf(wb[3], m4, d1);
            d1 = fmaf(wb[4], m5, d1);
            d2 = fmaf(wb[0], m2, d2); d2 = fmaf(wb[1], m3, d2);
            d2 = fmaf(wb[2], m4, d2); d2 = fmaf(wb[3], m5, d2);
            d2 = fmaf(wb[4], m6, d2);
            d3 = fmaf(wb[0], m3, d3); d3 = fmaf(wb[1], m4, d3);
            d3 = fmaf(wb[2], m5, d3); d3 = fmaf(wb[3], m6, d3);
            d3 = fmaf(wb[4], m7, d3);
        }
    }
    acc[0] = a0; acc[1] = a1; acc[2] = a2; acc[3] = a3;
    acc[4] = d0; acc[5] = d1; acc[6] = d2; acc[7] = d3;
}

__global__ __launch_bounds__(NT)
void snn_fused_kernel(const float* __restrict__ x,
                      const float* __restrict__ kern,
                      float* __restrict__ out)
{
    __shared__ __align__(16) float sm[NBUF * WBUFP];

    const int lane = threadIdx.x;
    const int tc   = lane & 7;        // col group: output cols x0+4tc .. +3
    const int rgL  = lane >> 3;       // row-pair group: rows y0+2rgL, +1

    const int x0 = blockIdx.x * QW;
    const int y0 = blockIdx.y * QH;

    // 5x5 weights in registers (uniform broadcast)
    float wgt[25];
#pragma unroll
    for (int i = 0; i < 25; i++) wgt[i] = __ldg(kern + i);

    // ---- Precompute this lane's PF cp.async fill slots (invariant over t) ----
    // Slot j copies float4 #(lane + j*32) of the 12-row x 10-float4 tile.
    // smem col 0 <-> global col x0-4 ; smem row 0 <-> global row y0-2.
    // Inactive slots target the per-buffer scratch at offset WBUF.
    int soff[PF], goff[PF], ssz[PF];
#pragma unroll
    for (int j = 0; j < PF; j++) {
        int i = lane + j * 32;
        if (i < FILLV) {
            int rr = i / F4R;
            int c4 = i - rr * F4R;
            int gy = y0 - 2 + rr;
            int gx = x0 - 4 + 4 * c4;
            bool v = (gy >= 0) && (gy < HH) && (gx >= 0) && (gx <= WW - 4);
            soff[j] = rr * SWP + 4 * c4;
            goff[j] = v ? (gy * WW + gx) : 0;
            ssz[j]  = v ? 16 : 0;
        } else {
            soff[j] = WBUF;   // per-buffer scratch, rotation-safe
            goff[j] = 0;
            ssz[j]  = 0;
        }
    }

    const uint32_t cb = (uint32_t)__cvta_generic_to_shared(&sm[0]);

    // ---- Prefetch timesteps 0..3 into buffers 0..3 (4 commit groups) ----
#pragma unroll
    for (int q = 0; q < 4; q++) {
        const float* xt = x + (size_t)q * HW;
        uint32_t dst = cb + (uint32_t)q * (4u * WBUFP);
#pragma unroll
        for (int j = 0; j < PF; j++) cp_async16(dst + 4u * soff[j], xt + goff[j], ssz[j]);
        cp_commit();
    }

    // LIF / LI state: 2 rows x 4 cols
    float s1[8], s2[8];
#pragma unroll
    for (int i = 0; i < 8; i++) { s1[i] = 0.f; s2[i] = 0.f; }

    const float* xp = x + 4 * (size_t)HW;                         // source for t+4
    float* op = out + (size_t)(y0 + 2 * rgL) * WW + x0 + 4 * tc;  // row 0 of pair
    const int rbase = (2 * rgL) * SWP + 4 * tc;                   // smem read base
    int rbuf = 0;                                                 // buffer of step t

    for (int t = 0; t < TT; t += 2) {
        cp_wait2();      // groups t, t+1 complete (t+2, t+3 may be pending)
        __syncwarp();    // cross-lane visibility of this iteration's tiles

        // Prefetch t+4 and t+5 into the two buffers freed last iteration
        {
            int b4 = rbuf + 4; if (b4 >= NBUF) b4 -= NBUF;
            int b5 = rbuf + 5; if (b5 >= NBUF) b5 -= NBUF;
            if (t + 4 < TT) {
                uint32_t dst = cb + (uint32_t)b4 * (4u * WBUFP);
#pragma unroll
                for (int j = 0; j < PF; j++)
                    cp_async16(dst + 4u * soff[j], xp + goff[j], ssz[j]);
            }
            cp_commit();
            if (t + 5 < TT) {
                uint32_t dst = cb + (uint32_t)b5 * (4u * WBUFP);
#pragma unroll
                for (int j = 0; j < PF; j++)
                    cp_async16(dst + 4u * soff[j], xp + HW + goff[j], ssz[j]);
            }
            cp_commit();
            xp += 2 * (size_t)HW;
        }

        // ---- Two independent convs (16 parallel FMA chains) ----
        int rb1 = rbuf + 1; if (rb1 >= NBUF) rb1 -= NBUF;
        float accA[8], accB[8];
        conv8(&sm[rbase + rbuf * WBUFP], wgt, accA);   // step t
        conv8(&sm[rbase + rb1  * WBUFP], wgt, accB);   // step t+1

        // ---- LIF + LI for step t, then t+1 (sequential state) ----
        float oA[8], oB[8];
#pragma unroll
        for (int i = 0; i < 8; i++) {
            float v = fmaf(ALPHA_LIF, s1[i], accA[i]);
            float spk = (v >= V_TH) ? 1.0f : 0.0f;
            s1[i] = fmaf(spk, -V_TH, v);
            s2[i] = fmaf(ALPHA_LI, s2[i], spk);
            oA[i] = s2[i];
            float v2 = fmaf(ALPHA_LIF, s1[i], accB[i]);
            float spk2 = (v2 >= V_TH) ? 1.0f : 0.0f;
            s1[i] = fmaf(spk2, -V_TH, v2);
            s2[i] = fmaf(ALPHA_LI, s2[i], spk2);
            oB[i] = s2[i];
        }

        // ---- Stores: 2 rows x 2 steps, vectorized ----
        float4 oA0 = {oA[0], oA[1], oA[2], oA[3]};
        float4 oA1 = {oA[4], oA[5], oA[6], oA[7]};
        float4 oB0 = {oB[0], oB[1], oB[2], oB[3]};
        float4 oB1 = {oB[4], oB[5], oB[6], oB[7]};
        *(float4*)op = oA0;
        *(float4*)(op + WW) = oA1;
        *(float4*)(op + HW) = oB0;
        *(float4*)(op + HW + WW) = oB1;
        op += 2 * (size_t)HW;

        rbuf += 2; if (rbuf >= NBUF) rbuf -= NBUF;
    }
}

extern "C" void kernel_launch(void* const* d_in, const int* in_sizes, int n_in,
                              void* d_out, int out_size)
{
    const float* x = (const float*)d_in[0];
    const float* k = (const float*)d_in[1];
    if (in_sizes[0] == 25) {  // defensive: swap if metadata order differs
        const float* tmp = x; x = k; k = tmp;
    }
    float* out = (float*)d_out;

    dim3 grid(WW / QW, HH / QH);   // 16 x 64 = 1024 one-warp blocks
    snn_fused_kernel<<<grid, NT>>>(x, k, out);
}